// round 15
// baseline (speedup 1.0000x reference)
#include <cuda_runtime.h>
#include <cuda_fp16.h>
#include <math.h>
#include <stdint.h>

// Problem constants
#define Bc    2
#define Tc    2048
#define Cc    2048
#define NHc   32
#define NGc   8
#define QPKc  4
#define HSc   64
#define QKVD  3072
#define BTc   (Bc*Tc)       // 4096

// Scratch (device globals: allocation-free)
__device__ __half g_xh [(size_t)BTc * Cc];
__device__ __half g_awh[(size_t)QKVD * Cc];
__device__ __half g_pwh[(size_t)Cc * Cc];
__device__ __half g_yh [(size_t)BTc * Cc];
__device__ __half g_qh[(size_t)Bc * NGc * QPKc * Tc * HSc];
__device__ __half g_kh[(size_t)Bc * NGc * Tc * HSc];
__device__ __half g_v [(size_t)Bc * NGc * Tc * HSc];   // natural [t][d]

#define QSCALE (0.125f * 1.44269504088896f)

// ---------------------------------------------------------------------------
// helpers
// ---------------------------------------------------------------------------
__device__ __forceinline__ uint32_t smem_u32(const void* p) {
    uint32_t a;
    asm("{ .reg .u64 t; cvta.to.shared.u64 t, %1; cvt.u32.u64 %0, t; }"
        : "=r"(a) : "l"(p));
    return a;
}
__device__ __forceinline__ void mma16(float* c, const uint32_t* a,
                                      uint32_t b0, uint32_t b1) {
    asm volatile(
        "mma.sync.aligned.m16n8k16.row.col.f32.f16.f16.f32 "
        "{%0,%1,%2,%3}, {%4,%5,%6,%7}, {%8,%9}, {%0,%1,%2,%3};\n"
        : "+f"(c[0]), "+f"(c[1]), "+f"(c[2]), "+f"(c[3])
        : "r"(a[0]), "r"(a[1]), "r"(a[2]), "r"(a[3]), "r"(b0), "r"(b1));
}
#define LDSM4(R0,R1,R2,R3,ADDR) \
    asm volatile("ldmatrix.sync.aligned.m8n8.x4.shared.b16 {%0,%1,%2,%3}, [%4];" \
        : "=r"(R0),"=r"(R1),"=r"(R2),"=r"(R3) : "r"(ADDR))
#define LDSM4T(R0,R1,R2,R3,ADDR) \
    asm volatile("ldmatrix.sync.aligned.m8n8.x4.trans.shared.b16 {%0,%1,%2,%3}, [%4];" \
        : "=r"(R0),"=r"(R1),"=r"(R2),"=r"(R3) : "r"(ADDR))
#define LDSM2T(R0,R1,ADDR) \
    asm volatile("ldmatrix.sync.aligned.m8n8.x2.trans.shared.b16 {%0,%1}, [%2];" \
        : "=r"(R0),"=r"(R1) : "r"(ADDR))

__device__ __forceinline__ uint32_t packh2(float x, float y) {
    __half2 h = __floats2half2_rn(x, y);
    return *(uint32_t*)&h;
}
__device__ __forceinline__ uint32_t exp2h2(float lo, float hi) {
    uint32_t p;
    asm("cvt.rn.f16x2.f32 %0, %1, %2;" : "=r"(p) : "f"(hi), "f"(lo));
    asm("ex2.approx.f16x2 %0, %0;" : "+r"(p));
    return p;
}
__device__ __forceinline__ void cp_async16(uint32_t saddr, const void* gaddr) {
    asm volatile("cp.async.cg.shared.global [%0], [%1], 16;"
                 :: "r"(saddr), "l"(gaddr));
}
#define CP_COMMIT()  asm volatile("cp.async.commit_group;" ::: "memory")
#define CP_WAIT1()   asm volatile("cp.async.wait_group 1;" ::: "memory")
#define CP_WAIT0()   asm volatile("cp.async.wait_group 0;" ::: "memory")

// ---------------------------------------------------------------------------
// fused fp32 -> fp16 convert for all three inputs (one launch)
// ---------------------------------------------------------------------------
__global__ void cvt3_kernel(const float* __restrict__ a, __half* __restrict__ da, int na,
                            const float* __restrict__ b, __half* __restrict__ db, int nb,
                            const float* __restrict__ c, __half* __restrict__ dc, int nc)
{
    int i = (blockIdx.x * blockDim.x + threadIdx.x) << 3;
    const float* s; __half* d;
    if (i < na)                { s = a + i;             d = da + i; }
    else if (i < na + nb)      { s = b + (i - na);      d = db + (i - na); }
    else if (i < na + nb + nc) { s = c + (i - na - nb); d = dc + (i - na - nb); }
    else return;
    float4 v0 = *(const float4*)s;
    float4 v1 = *(const float4*)(s + 4);
    uint4 o;
    o.x = packh2(v0.x, v0.y); o.y = packh2(v0.z, v0.w);
    o.z = packh2(v1.x, v1.y); o.w = packh2(v1.z, v1.w);
    *(uint4*)d = o;
}

// ---------------------------------------------------------------------------
// GEMM (NT) fp16 HMMA — R7 mainloop. CTA 128x128, BK=32, 256 threads,
// 3-stage cp.async, ldmatrix, pitch-20 smem.
// ROPE=true: staged-smem + streaming coalesced rope scatter epilogue (R13).
// ---------------------------------------------------------------------------
#define GPW 20
#define STG_W  (128 * GPW)
#define GSMEM  (3 * 2 * STG_W * 4)   // 61440 bytes

template <typename OT, bool ROPE>
__global__ __launch_bounds__(256, 2) void gemm_h(
    const __half* __restrict__ A, const __half* __restrict__ W,
    const float* __restrict__ bias, OT* __restrict__ Cm,
    const float* __restrict__ cosb, const float* __restrict__ sinb,
    int M, int N, int K)
{
    extern __shared__ uint32_t sh[];

    const int tid  = threadIdx.x;
    const int lane = tid & 31;
    const int warp = tid >> 5;
    const int wm = warp >> 2;
    const int wn = warp & 3;
    const int qr = lane >> 2;
    const int qc = lane & 3;

    const int m0 = blockIdx.y << 7;
    const int n0 = blockIdx.x << 7;

    const int lr = tid >> 1;
    const int lc = (tid & 1) << 1;

    const uint32_t sbase = smem_u32(sh);
    const __half* Ap = A + (size_t)(m0 + lr) * K;
    const __half* Wp = W + (size_t)(n0 + lr) * K;

    const uint32_t aoff =
        ((wm*64 + ((lane>>3)&1)*8 + (lane&7)) * GPW + (lane>>4)*4) * 4;
    const uint32_t woff =
        ((wn*32 + ((lane>>4)&1)*8 + (lane&7)) * GPW + ((lane>>3)&1)*4) * 4;

    float acc[4][4][4];
    #pragma unroll
    for (int i = 0; i < 4; i++)
        #pragma unroll
        for (int j = 0; j < 4; j++)
            #pragma unroll
            for (int c = 0; c < 4; c++) acc[i][j][c] = 0.f;

    const int nsteps = K >> 5;

    auto issue = [&](int stage, int ks) {
        const int kb = ks << 5;
        const uint32_t so = sbase + (uint32_t)(stage * 2 * STG_W * 4);
        #pragma unroll
        for (int j = 0; j < 2; j++) {
            const int c = lc + j;
            const uint32_t off = (uint32_t)((lr * GPW + c * 4) * 4);
            cp_async16(so + off, Ap + kb + c * 8);
            cp_async16(so + STG_W * 4 + off, Wp + kb + c * 8);
        }
        CP_COMMIT();
    };

    issue(0, 0);
    issue(1, 1);

    int stage = 0;
    for (int ks = 0; ks < nsteps; ks++) {
        if (ks + 1 < nsteps) CP_WAIT1(); else CP_WAIT0();
        __syncthreads();
        if (ks + 2 < nsteps) {
            int ns = stage + 2; if (ns >= 3) ns -= 3;
            issue(ns, ks + 2);
        }

        const uint32_t stb = sbase + (uint32_t)(stage * 2 * STG_W * 4);
        const uint32_t aAddr = stb + aoff;
        const uint32_t wAddr = stb + STG_W * 4 + woff;

        #pragma unroll
        for (int kt = 0; kt < 2; kt++) {
            uint32_t af[4][4], bf[4][2];
            #pragma unroll
            for (int mt = 0; mt < 4; mt++)
                LDSM4(af[mt][0], af[mt][1], af[mt][2], af[mt][3],
                      aAddr + (mt*16*GPW + kt*8) * 4);
            #pragma unroll
            for (int np = 0; np < 2; np++)
                LDSM4(bf[2*np][0], bf[2*np][1], bf[2*np+1][0], bf[2*np+1][1],
                      wAddr + (np*16*GPW + kt*8) * 4);
            #pragma unroll
            for (int mt = 0; mt < 4; mt++)
                #pragma unroll
                for (int nt = 0; nt < 4; nt++)
                    mma16(acc[mt][nt], af[mt], bf[nt][0], bf[nt][1]);
        }
        if (++stage == 3) stage = 0;
    }

    if (!ROPE) {
        #pragma unroll
        for (int nt = 0; nt < 4; nt++) {
            int col = n0 + wn*32 + nt*8 + 2*qc;
            float2 bia = *(const float2*)&bias[col];
            #pragma unroll
            for (int mt = 0; mt < 4; mt++) {
                int r0 = m0 + wm*64 + mt*16 + qr;
                float v00 = acc[mt][nt][0] + bia.x, v01 = acc[mt][nt][1] + bia.y;
                float v10 = acc[mt][nt][2] + bia.x, v11 = acc[mt][nt][3] + bia.y;
                if (sizeof(OT) == 4) {
                    *(float2*)&((float*)Cm)[(size_t)r0 * N + col]       = make_float2(v00, v01);
                    *(float2*)&((float*)Cm)[(size_t)(r0 + 8) * N + col] = make_float2(v10, v11);
                } else {
                    *(uint32_t*)&((__half*)Cm)[(size_t)r0 * N + col]       = packh2(v00, v01);
                    *(uint32_t*)&((__half*)Cm)[(size_t)(r0 + 8) * N + col] = packh2(v10, v11);
                }
            }
        }
    } else {
        // ---- stage fp16 tile in smem
        __syncthreads();
        uint32_t* St = sh; // 128 rows x 68 words
        #pragma unroll
        for (int nt = 0; nt < 4; nt++) {
            int colw = wn*16 + nt*4 + qc;
            float2 bia = *(const float2*)&bias[n0 + 2*colw];
            #pragma unroll
            for (int mt = 0; mt < 4; mt++) {
                int r0 = wm*64 + mt*16 + qr;
                St[r0*68 + colw]     = packh2(acc[mt][nt][0]+bia.x, acc[mt][nt][1]+bia.y);
                St[(r0+8)*68 + colw] = packh2(acc[mt][nt][2]+bia.x, acc[mt][nt][3]+bia.y);
            }
        }
        __syncthreads();

        // ---- streaming coalesced scatter
        const int c  = tid & 7;
        const int u0 = tid >> 3;
        const int d0 = c * 8;
        const float sgn = (c < 4) ? -1.f : 1.f;

        #pragma unroll 2
        for (int p = 0; p < 8; p++) {
            const int u  = p * 32 + u0;
            const int r  = u >> 1, hh = u & 1;
            const int hd = (n0 >> 6) + hh;
            const int g  = hd / 6, sl = hd % 6;
            const int rowg = m0 + r;
            const int t  = rowg & (Tc - 1);
            const int bb = rowg >> 11;
            const int bgq = bb * NGc + g;
            const uint32_t* src = St + r*68 + hh*32;

            uint4 own = *(const uint4*)(src + c*4);
            if (sl == QPKc + 1) {
                __half* dst = g_v + ((size_t)bgq*Tc + t)*HSc + d0;
                *(uint4*)dst = own;
            } else {
                uint4 par = *(const uint4*)(src + (c^4)*4);
                const float scl = (sl < QPKc) ? QSCALE : 1.f;
                float4 cA = *(const float4*)&cosb[t*64 + d0];
                float4 cB = *(const float4*)&cosb[t*64 + d0 + 4];
                float4 sA = *(const float4*)&sinb[t*64 + d0];
                float4 sB = *(const float4*)&sinb[t*64 + d0 + 4];
                const uint32_t* ow = (const uint32_t*)&own;
                const uint32_t* pw = (const uint32_t*)&par;
                uint4 o;
                uint32_t* oo = (uint32_t*)&o;
                const float cc[8] = {cA.x,cA.y,cA.z,cA.w,cB.x,cB.y,cB.z,cB.w};
                const float ss[8] = {sA.x,sA.y,sA.z,sA.w,sB.x,sB.y,sB.z,sB.w};
                #pragma unroll
                for (int j = 0; j < 4; j++) {
                    __half2 oh = *(const __half2*)&ow[j];
                    __half2 ph = *(const __half2*)&pw[j];
                    float f0 = __low2float(oh), f1 = __high2float(oh);
                    float p0 = __low2float(ph), p1 = __high2float(ph);
                    oo[j] = packh2((f0*cc[2*j]   + sgn*p0*ss[2*j])  *scl,
                                   (f1*cc[2*j+1] + sgn*p1*ss[2*j+1])*scl);
                }
                __half* dst = (sl < QPKc)
                    ? g_qh + (((size_t)bgq*QPKc + sl)*Tc + t)*HSc + d0
                    : g_kh + ((size_t)bgq*Tc + t)*HSc + d0;
                *(uint4*)dst = o;
            }
        }
    }
}

// ---------------------------------------------------------------------------
// Flash attention: 128 q-rows/block, 8 warps, cp.async double buffer,
// f16x2 exp2 softmax, ones-column MMA row-sum, per-warp diagonal-tile skip.
// NEW: per-warp intra-tile triangle limiting on diagonal tiles (lim):
//   S-GEMM np <= lim, softmax nt <= 2*lim+1, PV/ones kt <= lim.
// ---------------------------------------------------------------------------
#define PW 36
#define AQ_W   (128 * PW)
#define AKV_W  (64 * PW)
#define ASMEM  ((AQ_W + 4 * AKV_W) * 4)   // 55296 bytes

__global__ __launch_bounds__(256, 2) void attn_h()
{
    extern __shared__ uint32_t ash[];
    uint32_t* Qs = ash;

    const int tid  = threadIdx.x;
    const int lane = tid & 31;
    const int warp = tid >> 5;
    const int qr = lane >> 2;
    const int qc = lane & 3;

    const int q0   = (gridDim.x - 1 - blockIdx.x) << 7;
    const int slot = blockIdx.y;
    const int bg   = blockIdx.z;
    const int b = bg >> 3, gg = bg & 7;

    const __half* Qp = g_qh + ((size_t)(bg * QPKc + slot) * Tc + q0) * HSc;
    const __half* Kp = g_kh + (size_t)bg * Tc * HSc;
    const __half* Vp = g_v  + (size_t)bg * Tc * HSc;

    const uint32_t sb = smem_u32(ash);
    const uint32_t kwb[2] = { AQ_W,           AQ_W + 2*AKV_W };
    const uint32_t vwb[2] = { AQ_W + AKV_W,   AQ_W + 3*AKV_W };

    const uint32_t qAddr = sb +
        ((warp*16 + ((lane>>3)&1)*8 + (lane&7)) * PW + (lane>>4)*4) * 4;
    const uint32_t kOff =
        ((((lane>>4)&1)*8 + (lane&7)) * PW + ((lane>>3)&1)*4) * 4;
    const uint32_t vOff =
        ((((lane&7) + ((lane>>3)&1)*8) * PW) + ((lane>>4)&1)*4) * 4;
    const uint32_t oOff =
        ((((lane&7) + ((lane>>3)&1)*8) * PW) + 32) * 4;

    const int lrr = tid >> 2, lcq = tid & 3;

    auto issueKV = [&](int s, int st) {
        const int s0 = st << 6;
        const __half* kp = Kp + (size_t)(s0 + lrr) * HSc;
        const __half* vp = Vp + (size_t)(s0 + lrr) * HSc;
        const uint32_t kd = sb + (kwb[s] + lrr * PW) * 4;
        const uint32_t vd = sb + (vwb[s] + lrr * PW) * 4;
        #pragma unroll
        for (int j = 0; j < 2; j++) {
            const int c = lcq + 4 * j;
            cp_async16(kd + c * 16, kp + c * 8);
            cp_async16(vd + c * 16, vp + c * 8);
        }
        CP_COMMIT();
    };

    issueKV(0, 0);

    for (int i = tid; i < 128; i += 256) {
        int r = i & 63, s = i >> 6;
        uint32_t* p = ash + vwb[s] + r * PW + 32;
        p[0] = 0x3C003C00u; p[1] = 0x3C003C00u;
        p[2] = 0x3C003C00u; p[3] = 0x3C003C00u;
    }

    {
        const int r = tid >> 1, cq = tid & 1;
        #pragma unroll
        for (int j = 0; j < 4; j++) {
            int c = cq + 2 * j;
            uint4 v = *(const uint4*)(Qp + r * HSc + c * 8);
            *(uint4*)&Qs[r * PW + c * 4] = v;
        }
    }

    float co[8][4], co_l[4];
    #pragma unroll
    for (int nt = 0; nt < 8; nt++)
        #pragma unroll
        for (int c = 0; c < 4; c++) co[nt][c] = 0.f;
    #pragma unroll
    for (int c = 0; c < 4; c++) co_l[c] = 0.f;

    float mrow[2] = {-INFINITY, -INFINITY};

    const int ntiles = (q0 >> 6) + 2;
    const int wrow_min = q0 + warp*16;
    const int wrow_max = wrow_min + 15;

    for (int st = 0; st < ntiles; st++) {
        const int s0 = st << 6;
        const int cur = st & 1;

        CP_WAIT0();
        __syncthreads();
        if (st + 1 < ntiles) issueKV(cur ^ 1, st + 1);

        // Per-warp skip: tile entirely above this warp's diagonal.
        if (s0 > wrow_max) continue;

        // Triangle limit within diagonal tiles: key-groups 16*lim+15 max live.
        const int lim = min(3, (wrow_max - s0) >> 4);
        const int ntmax = 2*lim + 1;

        const uint32_t kAddr = sb + kwb[cur] * 4 + kOff;
        const uint32_t vAddr = sb + vwb[cur] * 4 + vOff;
        const uint32_t oAddr = sb + vwb[cur] * 4 + oOff;

        float cs[8][4];
        #pragma unroll
        for (int nt = 0; nt < 8; nt++)
            #pragma unroll
            for (int c = 0; c < 4; c++) cs[nt][c] = 0.f;

        #pragma unroll
        for (int kt = 0; kt < 4; kt++) {
            uint32_t a[4];
            LDSM4(a[0], a[1], a[2], a[3], qAddr + kt*32);
            #pragma unroll
            for (int np = 0; np < 4; np++) {
                if (np <= lim) {
                    uint32_t b0, b1, b2, b3;
                    LDSM4(b0, b1, b2, b3, kAddr + (np*16*PW + kt*8) * 4);
                    mma16(cs[2*np],   a, b0, b1);
                    mma16(cs[2*np+1], a, b2, b3);
                }
            }
        }

        const bool maskt = (s0 + 63 > wrow_min);
        const int r0g = wrow_min + qr;
        const int r1g = r0g + 8;
        float mx0 = mrow[0], mx1 = mrow[1];
        #pragma unroll
        for (int nt = 0; nt < 8; nt++) {
            if (nt > ntmax) break;
            int cbk = s0 + nt*8 + 2*qc;
            if (maskt) {
                if (cbk     > r0g) cs[nt][0] = -1e30f;
                if (cbk + 1 > r0g) cs[nt][1] = -1e30f;
                if (cbk     > r1g) cs[nt][2] = -1e30f;
                if (cbk + 1 > r1g) cs[nt][3] = -1e30f;
            }
            mx0 = fmaxf(mx0, fmaxf(cs[nt][0], cs[nt][1]));
            mx1 = fmaxf(mx1, fmaxf(cs[nt][2], cs[nt][3]));
        }
        mx0 = fmaxf(mx0, __shfl_xor_sync(0xffffffffu, mx0, 1));
        mx0 = fmaxf(mx0, __shfl_xor_sync(0xffffffffu, mx0, 2));
        mx1 = fmaxf(mx1, __shfl_xor_sync(0xffffffffu, mx1, 1));
        mx1 = fmaxf(mx1, __shfl_xor_sync(0xffffffffu, mx1, 2));

        float al0 = exp2f(mrow[0] - mx0);
        float al1 = exp2f(mrow[1] - mx1);
        mrow[0] = mx0; mrow[1] = mx1;

        uint32_t pa[4][4];
        #pragma unroll
        for (int nt = 0; nt < 8; nt++) {
            if (nt > ntmax) break;
            uint32_t p01 = exp2h2(cs[nt][0] - mx0, cs[nt][1] - mx0);
            uint32_t p23 = exp2h2(cs[nt][2] - mx1, cs[nt][3] - mx1);
            pa[nt >> 1][(nt & 1) << 1]       = p01;
            pa[nt >> 1][((nt & 1) << 1) + 1] = p23;
        }

        #pragma unroll
        for (int nt = 0; nt < 8; nt++) {
            co[nt][0] *= al0; co[nt][1] *= al0;
            co[nt][2] *= al1; co[nt][3] *= al1;
        }
        co_l[0] *= al0; co_l[1] *= al0;
        co_l[2] *= al1; co_l[3] *= al1;

        #pragma unroll
        for (int kt = 0; kt < 4; kt++) {
            if (kt > lim) break;
            #pragma unroll
            for (int np = 0; np < 4; np++) {
                uint32_t b0, b1, b2, b3;
                LDSM4T(b0, b1, b2, b3, vAddr + (kt*16*PW + np*8) * 4);
                mma16(co[2*np],   pa[kt], b0, b1);
                mma16(co[2*np+1], pa[kt], b2, b3);
            }
            uint32_t o0, o1;
            LDSM2T(o0, o1, oAddr + kt*16*PW*4);
            mma16(co_l, pa[kt], o0, o1);
        }
    }

    const float il0 = 1.f / co_l[0];
    const float il1 = 1.f / co_l[2];
    const int head = gg * QPKc + slot;
    const int r0g = q0 + warp*16 + qr;
    #pragma unroll
    for (int nt = 0; nt < 8; nt++) {
        int d = nt*8 + 2*qc;
        size_t o0 = ((size_t)(b * Tc + r0g)     * NHc + head) * HSc + d;
        size_t o1 = ((size_t)(b * Tc + r0g + 8) * NHc + head) * HSc + d;
        *(uint32_t*)&g_yh[o0] = packh2(co[nt][0] * il0, co[nt][1] * il0);
        *(uint32_t*)&g_yh[o1] = packh2(co[nt][2] * il1, co[nt][3] * il1);
    }
}

// ---------------------------------------------------------------------------
extern "C" void kernel_launch(void* const* d_in, const int* in_sizes, int n_in,
                              void* d_out, int out_size)
{
    const float* x      = (const float*)d_in[0];
    const float* cosb   = (const float*)d_in[1];
    const float* sinb   = (const float*)d_in[2];
    const float* attn_w = (const float*)d_in[3];
    const float* attn_b = (const float*)d_in[4];
    const float* proj_w = (const float*)d_in[5];
    const float* proj_b = (const float*)d_in[6];
    float* out = (float*)d_out;

    __half *xh, *awh, *pwh, *yh;
    cudaGetSymbolAddress((void**)&xh,  g_xh);
    cudaGetSymbolAddress((void**)&awh, g_awh);
    cudaGetSymbolAddress((void**)&pwh, g_pwh);
    cudaGetSymbolAddress((void**)&yh,  g_yh);

    cudaFuncSetAttribute((gemm_h<__half, true>),
                         cudaFuncAttributeMaxDynamicSharedMemorySize, GSMEM);
    cudaFuncSetAttribute((gemm_h<float, false>),
                         cudaFuncAttributeMaxDynamicSharedMemorySize, GSMEM);
    cudaFuncSetAttribute(attn_h,
                         cudaFuncAttributeMaxDynamicSharedMemorySize, ASMEM);

    // 0. fp32 -> fp16 converts (single launch)
    {
        int na = BTc * Cc, nb = QKVD * Cc, nc = Cc * Cc;
        int tot = na + nb + nc;
        cvt3_kernel<<<tot/8/256, 256>>>(x, xh, na, attn_w, awh, nb, proj_w, pwh, nc);
    }

    // 1. QKV GEMM with fused, coalesced rope epilogue -> g_qh / g_kh / g_v
    gemm_h<__half, true><<<dim3(QKVD/128, BTc/128), 256, GSMEM>>>(
        xh, awh, attn_b, (__half*)nullptr, cosb, sinb, BTc, QKVD, Cc);

    // 2. Flash attention
    attn_h<<<dim3(Tc/128, QPKc, Bc*NGc), 256, ASMEM>>>();

    // 3. Output projection (fp32 out)
    gemm_h<float, false><<<dim3(Cc/128, BTc/128), 256, GSMEM>>>(
        yh, pwh, proj_b, out, nullptr, nullptr, BTc, Cc, Cc);
}

// round 16
// speedup vs baseline: 1.5972x; 1.5972x over previous
#include <cuda_runtime.h>
#include <cuda_fp16.h>
#include <math.h>
#include <stdint.h>

// Problem constants
#define Bc    2
#define Tc    2048
#define Cc    2048
#define NHc   32
#define NGc   8
#define QPKc  4
#define HSc   64
#define QKVD  3072
#define BTc   (Bc*Tc)       // 4096

// Scratch (device globals: allocation-free)
__device__ __half g_xh [(size_t)BTc * Cc];
__device__ __half g_awh[(size_t)QKVD * Cc];
__device__ __half g_pwh[(size_t)Cc * Cc];
__device__ __half g_yh [(size_t)BTc * Cc];
__device__ __half g_qh[(size_t)Bc * NGc * QPKc * Tc * HSc];
__device__ __half g_kh[(size_t)Bc * NGc * Tc * HSc];
__device__ __half g_v [(size_t)Bc * NGc * Tc * HSc];   // natural [t][d]

#define QSCALE (0.125f * 1.44269504088896f)

// ---------------------------------------------------------------------------
// helpers
// ---------------------------------------------------------------------------
__device__ __forceinline__ uint32_t smem_u32(const void* p) {
    uint32_t a;
    asm("{ .reg .u64 t; cvta.to.shared.u64 t, %1; cvt.u32.u64 %0, t; }"
        : "=r"(a) : "l"(p));
    return a;
}
__device__ __forceinline__ void mma16(float* c, const uint32_t* a,
                                      uint32_t b0, uint32_t b1) {
    asm volatile(
        "mma.sync.aligned.m16n8k16.row.col.f32.f16.f16.f32 "
        "{%0,%1,%2,%3}, {%4,%5,%6,%7}, {%8,%9}, {%0,%1,%2,%3};\n"
        : "+f"(c[0]), "+f"(c[1]), "+f"(c[2]), "+f"(c[3])
        : "r"(a[0]), "r"(a[1]), "r"(a[2]), "r"(a[3]), "r"(b0), "r"(b1));
}
#define LDSM4(R0,R1,R2,R3,ADDR) \
    asm volatile("ldmatrix.sync.aligned.m8n8.x4.shared.b16 {%0,%1,%2,%3}, [%4];" \
        : "=r"(R0),"=r"(R1),"=r"(R2),"=r"(R3) : "r"(ADDR))
#define LDSM4T(R0,R1,R2,R3,ADDR) \
    asm volatile("ldmatrix.sync.aligned.m8n8.x4.trans.shared.b16 {%0,%1,%2,%3}, [%4];" \
        : "=r"(R0),"=r"(R1),"=r"(R2),"=r"(R3) : "r"(ADDR))
#define LDSM2T(R0,R1,ADDR) \
    asm volatile("ldmatrix.sync.aligned.m8n8.x2.trans.shared.b16 {%0,%1}, [%2];" \
        : "=r"(R0),"=r"(R1) : "r"(ADDR))

__device__ __forceinline__ uint32_t packh2(float x, float y) {
    __half2 h = __floats2half2_rn(x, y);
    return *(uint32_t*)&h;
}
__device__ __forceinline__ uint32_t exp2h2(float lo, float hi) {
    uint32_t p;
    asm("cvt.rn.f16x2.f32 %0, %1, %2;" : "=r"(p) : "f"(hi), "f"(lo));
    asm("ex2.approx.f16x2 %0, %0;" : "+r"(p));
    return p;
}
__device__ __forceinline__ void cp_async16(uint32_t saddr, const void* gaddr) {
    asm volatile("cp.async.cg.shared.global [%0], [%1], 16;"
                 :: "r"(saddr), "l"(gaddr));
}
#define CP_COMMIT()  asm volatile("cp.async.commit_group;" ::: "memory")
#define CP_WAIT1()   asm volatile("cp.async.wait_group 1;" ::: "memory")
#define CP_WAIT0()   asm volatile("cp.async.wait_group 0;" ::: "memory")

// ---------------------------------------------------------------------------
// fused fp32 -> fp16 convert for all three inputs (one launch)
// ---------------------------------------------------------------------------
__global__ void cvt3_kernel(const float* __restrict__ a, __half* __restrict__ da, int na,
                            const float* __restrict__ b, __half* __restrict__ db, int nb,
                            const float* __restrict__ c, __half* __restrict__ dc, int nc)
{
    int i = (blockIdx.x * blockDim.x + threadIdx.x) << 3;
    const float* s; __half* d;
    if (i < na)                { s = a + i;             d = da + i; }
    else if (i < na + nb)      { s = b + (i - na);      d = db + (i - na); }
    else if (i < na + nb + nc) { s = c + (i - na - nb); d = dc + (i - na - nb); }
    else return;
    float4 v0 = *(const float4*)s;
    float4 v1 = *(const float4*)(s + 4);
    uint4 o;
    o.x = packh2(v0.x, v0.y); o.y = packh2(v0.z, v0.w);
    o.z = packh2(v1.x, v1.y); o.w = packh2(v1.z, v1.w);
    *(uint4*)d = o;
}

// ---------------------------------------------------------------------------
// GEMM (NT) fp16 HMMA — R7 mainloop. CTA 128x128, BK=32, 256 threads,
// 3-stage cp.async, ldmatrix, pitch-20 smem.
// ROPE=true: staged-smem + streaming coalesced rope scatter epilogue (R13).
// ---------------------------------------------------------------------------
#define GPW 20
#define STG_W  (128 * GPW)
#define GSMEM  (3 * 2 * STG_W * 4)   // 61440 bytes

template <typename OT, bool ROPE>
__global__ __launch_bounds__(256, 2) void gemm_h(
    const __half* __restrict__ A, const __half* __restrict__ W,
    const float* __restrict__ bias, OT* __restrict__ Cm,
    const float* __restrict__ cosb, const float* __restrict__ sinb,
    int M, int N, int K)
{
    extern __shared__ uint32_t sh[];

    const int tid  = threadIdx.x;
    const int lane = tid & 31;
    const int warp = tid >> 5;
    const int wm = warp >> 2;
    const int wn = warp & 3;
    const int qr = lane >> 2;
    const int qc = lane & 3;

    const int m0 = blockIdx.y << 7;
    const int n0 = blockIdx.x << 7;

    const int lr = tid >> 1;
    const int lc = (tid & 1) << 1;

    const uint32_t sbase = smem_u32(sh);
    const __half* Ap = A + (size_t)(m0 + lr) * K;
    const __half* Wp = W + (size_t)(n0 + lr) * K;

    const uint32_t aoff =
        ((wm*64 + ((lane>>3)&1)*8 + (lane&7)) * GPW + (lane>>4)*4) * 4;
    const uint32_t woff =
        ((wn*32 + ((lane>>4)&1)*8 + (lane&7)) * GPW + ((lane>>3)&1)*4) * 4;

    float acc[4][4][4];
    #pragma unroll
    for (int i = 0; i < 4; i++)
        #pragma unroll
        for (int j = 0; j < 4; j++)
            #pragma unroll
            for (int c = 0; c < 4; c++) acc[i][j][c] = 0.f;

    const int nsteps = K >> 5;

    auto issue = [&](int stage, int ks) {
        const int kb = ks << 5;
        const uint32_t so = sbase + (uint32_t)(stage * 2 * STG_W * 4);
        #pragma unroll
        for (int j = 0; j < 2; j++) {
            const int c = lc + j;
            const uint32_t off = (uint32_t)((lr * GPW + c * 4) * 4);
            cp_async16(so + off, Ap + kb + c * 8);
            cp_async16(so + STG_W * 4 + off, Wp + kb + c * 8);
        }
        CP_COMMIT();
    };

    issue(0, 0);
    issue(1, 1);

    int stage = 0;
    for (int ks = 0; ks < nsteps; ks++) {
        if (ks + 1 < nsteps) CP_WAIT1(); else CP_WAIT0();
        __syncthreads();
        if (ks + 2 < nsteps) {
            int ns = stage + 2; if (ns >= 3) ns -= 3;
            issue(ns, ks + 2);
        }

        const uint32_t stb = sbase + (uint32_t)(stage * 2 * STG_W * 4);
        const uint32_t aAddr = stb + aoff;
        const uint32_t wAddr = stb + STG_W * 4 + woff;

        #pragma unroll
        for (int kt = 0; kt < 2; kt++) {
            uint32_t af[4][4], bf[4][2];
            #pragma unroll
            for (int mt = 0; mt < 4; mt++)
                LDSM4(af[mt][0], af[mt][1], af[mt][2], af[mt][3],
                      aAddr + (mt*16*GPW + kt*8) * 4);
            #pragma unroll
            for (int np = 0; np < 2; np++)
                LDSM4(bf[2*np][0], bf[2*np][1], bf[2*np+1][0], bf[2*np+1][1],
                      wAddr + (np*16*GPW + kt*8) * 4);
            #pragma unroll
            for (int mt = 0; mt < 4; mt++)
                #pragma unroll
                for (int nt = 0; nt < 4; nt++)
                    mma16(acc[mt][nt], af[mt], bf[nt][0], bf[nt][1]);
        }
        if (++stage == 3) stage = 0;
    }

    if (!ROPE) {
        #pragma unroll
        for (int nt = 0; nt < 4; nt++) {
            int col = n0 + wn*32 + nt*8 + 2*qc;
            float2 bia = *(const float2*)&bias[col];
            #pragma unroll
            for (int mt = 0; mt < 4; mt++) {
                int r0 = m0 + wm*64 + mt*16 + qr;
                float v00 = acc[mt][nt][0] + bia.x, v01 = acc[mt][nt][1] + bia.y;
                float v10 = acc[mt][nt][2] + bia.x, v11 = acc[mt][nt][3] + bia.y;
                if (sizeof(OT) == 4) {
                    *(float2*)&((float*)Cm)[(size_t)r0 * N + col]       = make_float2(v00, v01);
                    *(float2*)&((float*)Cm)[(size_t)(r0 + 8) * N + col] = make_float2(v10, v11);
                } else {
                    *(uint32_t*)&((__half*)Cm)[(size_t)r0 * N + col]       = packh2(v00, v01);
                    *(uint32_t*)&((__half*)Cm)[(size_t)(r0 + 8) * N + col] = packh2(v10, v11);
                }
            }
        }
    } else {
        // ---- stage fp16 tile in smem
        __syncthreads();
        uint32_t* St = sh; // 128 rows x 68 words
        #pragma unroll
        for (int nt = 0; nt < 4; nt++) {
            int colw = wn*16 + nt*4 + qc;
            float2 bia = *(const float2*)&bias[n0 + 2*colw];
            #pragma unroll
            for (int mt = 0; mt < 4; mt++) {
                int r0 = wm*64 + mt*16 + qr;
                St[r0*68 + colw]     = packh2(acc[mt][nt][0]+bia.x, acc[mt][nt][1]+bia.y);
                St[(r0+8)*68 + colw] = packh2(acc[mt][nt][2]+bia.x, acc[mt][nt][3]+bia.y);
            }
        }
        __syncthreads();

        // ---- streaming coalesced scatter
        const int c  = tid & 7;
        const int u0 = tid >> 3;
        const int d0 = c * 8;
        const float sgn = (c < 4) ? -1.f : 1.f;

        #pragma unroll 2
        for (int p = 0; p < 8; p++) {
            const int u  = p * 32 + u0;
            const int r  = u >> 1, hh = u & 1;
            const int hd = (n0 >> 6) + hh;
            const int g  = hd / 6, sl = hd % 6;
            const int rowg = m0 + r;
            const int t  = rowg & (Tc - 1);
            const int bb = rowg >> 11;
            const int bgq = bb * NGc + g;
            const uint32_t* src = St + r*68 + hh*32;

            uint4 own = *(const uint4*)(src + c*4);
            if (sl == QPKc + 1) {
                __half* dst = g_v + ((size_t)bgq*Tc + t)*HSc + d0;
                *(uint4*)dst = own;
            } else {
                uint4 par = *(const uint4*)(src + (c^4)*4);
                const float scl = (sl < QPKc) ? QSCALE : 1.f;
                float4 cA = *(const float4*)&cosb[t*64 + d0];
                float4 cB = *(const float4*)&cosb[t*64 + d0 + 4];
                float4 sA = *(const float4*)&sinb[t*64 + d0];
                float4 sB = *(const float4*)&sinb[t*64 + d0 + 4];
                const uint32_t* ow = (const uint32_t*)&own;
                const uint32_t* pw = (const uint32_t*)&par;
                uint4 o;
                uint32_t* oo = (uint32_t*)&o;
                const float cc[8] = {cA.x,cA.y,cA.z,cA.w,cB.x,cB.y,cB.z,cB.w};
                const float ss[8] = {sA.x,sA.y,sA.z,sA.w,sB.x,sB.y,sB.z,sB.w};
                #pragma unroll
                for (int j = 0; j < 4; j++) {
                    __half2 oh = *(const __half2*)&ow[j];
                    __half2 ph = *(const __half2*)&pw[j];
                    float f0 = __low2float(oh), f1 = __high2float(oh);
                    float p0 = __low2float(ph), p1 = __high2float(ph);
                    oo[j] = packh2((f0*cc[2*j]   + sgn*p0*ss[2*j])  *scl,
                                   (f1*cc[2*j+1] + sgn*p1*ss[2*j+1])*scl);
                }
                __half* dst = (sl < QPKc)
                    ? g_qh + (((size_t)bgq*QPKc + sl)*Tc + t)*HSc + d0
                    : g_kh + ((size_t)bgq*Tc + t)*HSc + d0;
                *(uint4*)dst = o;
            }
        }
    }
}

// ---------------------------------------------------------------------------
// Attention tile body — compile-time LIM (key-group limit) and MASKT.
// All loop bounds constant -> full unroll, register-resident arrays.
// ---------------------------------------------------------------------------
#define PW 36
#define AQ_W   (128 * PW)
#define AKV_W  (64 * PW)
#define ASMEM  ((AQ_W + 4 * AKV_W) * 4)   // 55296 bytes

template <int LIM, bool MASKT>
__device__ __forceinline__ void attn_tile(
    uint32_t qAddr, uint32_t kAddr, uint32_t vAddr, uint32_t oAddr,
    int s0, int wrow_min, int qr, int qc,
    float (&co)[8][4], float (&co_l)[4], float (&mrow)[2])
{
    constexpr int NT = 2 * (LIM + 1);
    float cs[NT][4];
    #pragma unroll
    for (int nt = 0; nt < NT; nt++)
        #pragma unroll
        for (int c = 0; c < 4; c++) cs[nt][c] = 0.f;

    // S = Q K^T (restricted to live key groups)
    #pragma unroll
    for (int kt = 0; kt < 4; kt++) {
        uint32_t a[4];
        LDSM4(a[0], a[1], a[2], a[3], qAddr + kt*32);
        #pragma unroll
        for (int np = 0; np <= LIM; np++) {
            uint32_t b0, b1, b2, b3;
            LDSM4(b0, b1, b2, b3, kAddr + (np*16*PW + kt*8) * 4);
            mma16(cs[2*np],   a, b0, b1);
            mma16(cs[2*np+1], a, b2, b3);
        }
    }

    // mask + row max
    const int r0g = wrow_min + qr;
    const int r1g = r0g + 8;
    float mx0 = mrow[0], mx1 = mrow[1];
    #pragma unroll
    for (int nt = 0; nt < NT; nt++) {
        int cbk = s0 + nt*8 + 2*qc;
        if (MASKT) {
            if (cbk     > r0g) cs[nt][0] = -1e30f;
            if (cbk + 1 > r0g) cs[nt][1] = -1e30f;
            if (cbk     > r1g) cs[nt][2] = -1e30f;
            if (cbk + 1 > r1g) cs[nt][3] = -1e30f;
        }
        mx0 = fmaxf(mx0, fmaxf(cs[nt][0], cs[nt][1]));
        mx1 = fmaxf(mx1, fmaxf(cs[nt][2], cs[nt][3]));
    }
    mx0 = fmaxf(mx0, __shfl_xor_sync(0xffffffffu, mx0, 1));
    mx0 = fmaxf(mx0, __shfl_xor_sync(0xffffffffu, mx0, 2));
    mx1 = fmaxf(mx1, __shfl_xor_sync(0xffffffffu, mx1, 1));
    mx1 = fmaxf(mx1, __shfl_xor_sync(0xffffffffu, mx1, 2));

    float al0 = exp2f(mrow[0] - mx0);
    float al1 = exp2f(mrow[1] - mx1);
    mrow[0] = mx0; mrow[1] = mx1;

    // P = exp2(cs - mx) in fp16x2 = PV A-fragments
    uint32_t pa[LIM + 1][4];
    #pragma unroll
    for (int nt = 0; nt < NT; nt++) {
        uint32_t p01 = exp2h2(cs[nt][0] - mx0, cs[nt][1] - mx0);
        uint32_t p23 = exp2h2(cs[nt][2] - mx1, cs[nt][3] - mx1);
        pa[nt >> 1][(nt & 1) << 1]       = p01;
        pa[nt >> 1][((nt & 1) << 1) + 1] = p23;
    }

    // rescale O, l
    #pragma unroll
    for (int nt = 0; nt < 8; nt++) {
        co[nt][0] *= al0; co[nt][1] *= al0;
        co[nt][2] *= al1; co[nt][3] *= al1;
    }
    co_l[0] *= al0; co_l[1] *= al0;
    co_l[2] *= al1; co_l[3] *= al1;

    // O += P V ; l += P @ ones (restricted key groups)
    #pragma unroll
    for (int kt = 0; kt <= LIM; kt++) {
        #pragma unroll
        for (int np = 0; np < 4; np++) {
            uint32_t b0, b1, b2, b3;
            LDSM4T(b0, b1, b2, b3, vAddr + (kt*16*PW + np*8) * 4);
            mma16(co[2*np],   pa[kt], b0, b1);
            mma16(co[2*np+1], pa[kt], b2, b3);
        }
        uint32_t o0, o1;
        LDSM2T(o0, o1, oAddr + kt*16*PW*4);
        mma16(co_l, pa[kt], o0, o1);
    }
}

// ---------------------------------------------------------------------------
// Flash attention: 128 q-rows/block, 8 warps, cp.async double buffer,
// f16x2 exp2 softmax, ones-column row-sum, per-warp diagonal handling via
// compile-time-specialized tile bodies (LIM in {0,1,2,3}, full = <3,false>).
// ---------------------------------------------------------------------------
__global__ __launch_bounds__(256, 2) void attn_h()
{
    extern __shared__ uint32_t ash[];
    uint32_t* Qs = ash;

    const int tid  = threadIdx.x;
    const int lane = tid & 31;
    const int warp = tid >> 5;
    const int qr = lane >> 2;
    const int qc = lane & 3;

    const int q0   = (gridDim.x - 1 - blockIdx.x) << 7;
    const int slot = blockIdx.y;
    const int bg   = blockIdx.z;
    const int b = bg >> 3, gg = bg & 7;

    const __half* Qp = g_qh + ((size_t)(bg * QPKc + slot) * Tc + q0) * HSc;
    const __half* Kp = g_kh + (size_t)bg * Tc * HSc;
    const __half* Vp = g_v  + (size_t)bg * Tc * HSc;

    const uint32_t sb = smem_u32(ash);
    const uint32_t kwb[2] = { AQ_W,           AQ_W + 2*AKV_W };
    const uint32_t vwb[2] = { AQ_W + AKV_W,   AQ_W + 3*AKV_W };

    const uint32_t qAddr = sb +
        ((warp*16 + ((lane>>3)&1)*8 + (lane&7)) * PW + (lane>>4)*4) * 4;
    const uint32_t kOff =
        ((((lane>>4)&1)*8 + (lane&7)) * PW + ((lane>>3)&1)*4) * 4;
    const uint32_t vOff =
        ((((lane&7) + ((lane>>3)&1)*8) * PW) + ((lane>>4)&1)*4) * 4;
    const uint32_t oOff =
        ((((lane&7) + ((lane>>3)&1)*8) * PW) + 32) * 4;

    const int lrr = tid >> 2, lcq = tid & 3;

    auto issueKV = [&](int s, int st) {
        const int s0 = st << 6;
        const __half* kp = Kp + (size_t)(s0 + lrr) * HSc;
        const __half* vp = Vp + (size_t)(s0 + lrr) * HSc;
        const uint32_t kd = sb + (kwb[s] + lrr * PW) * 4;
        const uint32_t vd = sb + (vwb[s] + lrr * PW) * 4;
        #pragma unroll
        for (int j = 0; j < 2; j++) {
            const int c = lcq + 4 * j;
            cp_async16(kd + c * 16, kp + c * 8);
            cp_async16(vd + c * 16, vp + c * 8);
        }
        CP_COMMIT();
    };

    issueKV(0, 0);

    for (int i = tid; i < 128; i += 256) {
        int r = i & 63, s = i >> 6;
        uint32_t* p = ash + vwb[s] + r * PW + 32;
        p[0] = 0x3C003C00u; p[1] = 0x3C003C00u;
        p[2] = 0x3C003C00u; p[3] = 0x3C003C00u;
    }

    {
        const int r = tid >> 1, cq = tid & 1;
        #pragma unroll
        for (int j = 0; j < 4; j++) {
            int c = cq + 2 * j;
            uint4 v = *(const uint4*)(Qp + r * HSc + c * 8);
            *(uint4*)&Qs[r * PW + c * 4] = v;
        }
    }

    float co[8][4], co_l[4];
    #pragma unroll
    for (int nt = 0; nt < 8; nt++)
        #pragma unroll
        for (int c = 0; c < 4; c++) co[nt][c] = 0.f;
    #pragma unroll
    for (int c = 0; c < 4; c++) co_l[c] = 0.f;

    float mrow[2] = {-INFINITY, -INFINITY};

    const int ntiles = (q0 >> 6) + 2;
    const int wrow_min = q0 + warp*16;
    const int wrow_max = wrow_min + 15;

    for (int st = 0; st < ntiles; st++) {
        const int s0 = st << 6;
        const int cur = st & 1;

        CP_WAIT0();
        __syncthreads();
        if (st + 1 < ntiles) issueKV(cur ^ 1, st + 1);

        const int d = wrow_max - s0;      // always == 15 (mod 16)
        if (d < 0) continue;              // fully-masked tile: identity

        const uint32_t kAddr = sb + kwb[cur] * 4 + kOff;
        const uint32_t vAddr = sb + vwb[cur] * 4 + vOff;
        const uint32_t oAddr = sb + vwb[cur] * 4 + oOff;

        if (d >= 64) {
            // full tile, provably unmasked (d >= 79 given d % 16 == 15)
            attn_tile<3, false>(qAddr, kAddr, vAddr, oAddr,
                                s0, wrow_min, qr, qc, co, co_l, mrow);
        } else {
            switch (d >> 4) {
            case 3: attn_tile<3, true>(qAddr, kAddr, vAddr, oAddr,
                                       s0, wrow_min, qr, qc, co, co_l, mrow); break;
            case 2: attn_tile<2, true>(qAddr, kAddr, vAddr, oAddr,
                                       s0, wrow_min, qr, qc, co, co_l, mrow); break;
            case 1: attn_tile<1, true>(qAddr, kAddr, vAddr, oAddr,
                                       s0, wrow_min, qr, qc, co, co_l, mrow); break;
            default: attn_tile<0, true>(qAddr, kAddr, vAddr, oAddr,
                                        s0, wrow_min, qr, qc, co, co_l, mrow); break;
            }
        }
    }

    const float il0 = 1.f / co_l[0];
    const float il1 = 1.f / co_l[2];
    const int head = gg * QPKc + slot;
    const int r0g = q0 + warp*16 + qr;
    #pragma unroll
    for (int nt = 0; nt < 8; nt++) {
        int d = nt*8 + 2*qc;
        size_t o0 = ((size_t)(b * Tc + r0g)     * NHc + head) * HSc + d;
        size_t o1 = ((size_t)(b * Tc + r0g + 8) * NHc + head) * HSc + d;
        *(uint32_t*)&g_yh[o0] = packh2(co[nt][0] * il0, co[nt][1] * il0);
        *(uint32_t*)&g_yh[o1] = packh2(co[nt][2] * il1, co[nt][3] * il1);
    }
}

// ---------------------------------------------------------------------------
extern "C" void kernel_launch(void* const* d_in, const int* in_sizes, int n_in,
                              void* d_out, int out_size)
{
    const float* x      = (const float*)d_in[0];
    const float* cosb   = (const float*)d_in[1];
    const float* sinb   = (const float*)d_in[2];
    const float* attn_w = (const float*)d_in[3];
    const float* attn_b = (const float*)d_in[4];
    const float* proj_w = (const float*)d_in[5];
    const float* proj_b = (const float*)d_in[6];
    float* out = (float*)d_out;

    __half *xh, *awh, *pwh, *yh;
    cudaGetSymbolAddress((void**)&xh,  g_xh);
    cudaGetSymbolAddress((void**)&awh, g_awh);
    cudaGetSymbolAddress((void**)&pwh, g_pwh);
    cudaGetSymbolAddress((void**)&yh,  g_yh);

    cudaFuncSetAttribute((gemm_h<__half, true>),
                         cudaFuncAttributeMaxDynamicSharedMemorySize, GSMEM);
    cudaFuncSetAttribute((gemm_h<float, false>),
                         cudaFuncAttributeMaxDynamicSharedMemorySize, GSMEM);
    cudaFuncSetAttribute(attn_h,
                         cudaFuncAttributeMaxDynamicSharedMemorySize, ASMEM);

    // 0. fp32 -> fp16 converts (single launch)
    {
        int na = BTc * Cc, nb = QKVD * Cc, nc = Cc * Cc;
        int tot = na + nb + nc;
        cvt3_kernel<<<tot/8/256, 256>>>(x, xh, na, attn_w, awh, nb, proj_w, pwh, nc);
    }

    // 1. QKV GEMM with fused, coalesced rope epilogue -> g_qh / g_kh / g_v
    gemm_h<__half, true><<<dim3(QKVD/128, BTc/128), 256, GSMEM>>>(
        xh, awh, attn_b, (__half*)nullptr, cosb, sinb, BTc, QKVD, Cc);

    // 2. Flash attention
    attn_h<<<dim3(Tc/128, QPKc, Bc*NGc), 256, ASMEM>>>();

    // 3. Output projection (fp32 out)
    gemm_h<float, false><<<dim3(Cc/128, BTc/128), 256, GSMEM>>>(
        yh, pwh, proj_b, out, nullptr, nullptr, BTc, Cc, Cc);
}

// round 17
// speedup vs baseline: 1.5975x; 1.0002x over previous
#include <cuda_runtime.h>
#include <cuda_fp16.h>
#include <math.h>
#include <stdint.h>

// Problem constants
#define Bc    2
#define Tc    2048
#define Cc    2048
#define NHc   32
#define NGc   8
#define QPKc  4
#define HSc   64
#define QKVD  3072
#define BTc   (Bc*Tc)       // 4096

// Scratch (device globals: allocation-free)
__device__ __half g_xh [(size_t)BTc * Cc];
__device__ __half g_awh[(size_t)QKVD * Cc];
__device__ __half g_pwh[(size_t)Cc * Cc];
__device__ __half g_yh [(size_t)BTc * Cc];
__device__ __half g_qh[(size_t)Bc * NGc * QPKc * Tc * HSc];
__device__ __half g_kh[(size_t)Bc * NGc * Tc * HSc];
__device__ __half g_v [(size_t)Bc * NGc * Tc * HSc];   // natural [t][d]

#define QSCALE (0.125f * 1.44269504088896f)

// ---------------------------------------------------------------------------
// helpers
// ---------------------------------------------------------------------------
__device__ __forceinline__ uint32_t smem_u32(const void* p) {
    uint32_t a;
    asm("{ .reg .u64 t; cvta.to.shared.u64 t, %1; cvt.u32.u64 %0, t; }"
        : "=r"(a) : "l"(p));
    return a;
}
__device__ __forceinline__ void mma16(float* c, const uint32_t* a,
                                      uint32_t b0, uint32_t b1) {
    asm volatile(
        "mma.sync.aligned.m16n8k16.row.col.f32.f16.f16.f32 "
        "{%0,%1,%2,%3}, {%4,%5,%6,%7}, {%8,%9}, {%0,%1,%2,%3};\n"
        : "+f"(c[0]), "+f"(c[1]), "+f"(c[2]), "+f"(c[3])
        : "r"(a[0]), "r"(a[1]), "r"(a[2]), "r"(a[3]), "r"(b0), "r"(b1));
}
#define LDSM4(R0,R1,R2,R3,ADDR) \
    asm volatile("ldmatrix.sync.aligned.m8n8.x4.shared.b16 {%0,%1,%2,%3}, [%4];" \
        : "=r"(R0),"=r"(R1),"=r"(R2),"=r"(R3) : "r"(ADDR))
#define LDSM4T(R0,R1,R2,R3,ADDR) \
    asm volatile("ldmatrix.sync.aligned.m8n8.x4.trans.shared.b16 {%0,%1,%2,%3}, [%4];" \
        : "=r"(R0),"=r"(R1),"=r"(R2),"=r"(R3) : "r"(ADDR))
#define LDSM2T(R0,R1,ADDR) \
    asm volatile("ldmatrix.sync.aligned.m8n8.x2.trans.shared.b16 {%0,%1}, [%2];" \
        : "=r"(R0),"=r"(R1) : "r"(ADDR))

__device__ __forceinline__ uint32_t packh2(float x, float y) {
    __half2 h = __floats2half2_rn(x, y);
    return *(uint32_t*)&h;
}
__device__ __forceinline__ uint32_t exp2h2(float lo, float hi) {
    uint32_t p;
    asm("cvt.rn.f16x2.f32 %0, %1, %2;" : "=r"(p) : "f"(hi), "f"(lo));
    asm("ex2.approx.f16x2 %0, %0;" : "+r"(p));
    return p;
}
__device__ __forceinline__ void cp_async16(uint32_t saddr, const void* gaddr) {
    asm volatile("cp.async.cg.shared.global [%0], [%1], 16;"
                 :: "r"(saddr), "l"(gaddr));
}
#define CP_COMMIT()  asm volatile("cp.async.commit_group;" ::: "memory")
#define CP_WAIT1()   asm volatile("cp.async.wait_group 1;" ::: "memory")
#define CP_WAIT0()   asm volatile("cp.async.wait_group 0;" ::: "memory")

// ---------------------------------------------------------------------------
// fused fp32 -> fp16 convert (x + attn_w only; proj_w rides inside attn_h)
// ---------------------------------------------------------------------------
__global__ void cvt2_kernel(const float* __restrict__ a, __half* __restrict__ da, int na,
                            const float* __restrict__ b, __half* __restrict__ db, int nb)
{
    int i = (blockIdx.x * blockDim.x + threadIdx.x) << 3;
    const float* s; __half* d;
    if (i < na)           { s = a + i;        d = da + i; }
    else if (i < na + nb) { s = b + (i - na); d = db + (i - na); }
    else return;
    float4 v0 = *(const float4*)s;
    float4 v1 = *(const float4*)(s + 4);
    uint4 o;
    o.x = packh2(v0.x, v0.y); o.y = packh2(v0.z, v0.w);
    o.z = packh2(v1.x, v1.y); o.w = packh2(v1.z, v1.w);
    *(uint4*)d = o;
}

// ---------------------------------------------------------------------------
// GEMM (NT) fp16 HMMA — R7 mainloop. CTA 128x128, BK=32, 256 threads,
// 3-stage cp.async, ldmatrix, pitch-20 smem.
// ROPE=true: staged-smem + streaming coalesced rope scatter epilogue (R13).
// ---------------------------------------------------------------------------
#define GPW 20
#define STG_W  (128 * GPW)
#define GSMEM  (3 * 2 * STG_W * 4)   // 61440 bytes

template <typename OT, bool ROPE>
__global__ __launch_bounds__(256, 2) void gemm_h(
    const __half* __restrict__ A, const __half* __restrict__ W,
    const float* __restrict__ bias, OT* __restrict__ Cm,
    const float* __restrict__ cosb, const float* __restrict__ sinb,
    int M, int N, int K)
{
    extern __shared__ uint32_t sh[];

    const int tid  = threadIdx.x;
    const int lane = tid & 31;
    const int warp = tid >> 5;
    const int wm = warp >> 2;
    const int wn = warp & 3;
    const int qr = lane >> 2;
    const int qc = lane & 3;

    const int m0 = blockIdx.y << 7;
    const int n0 = blockIdx.x << 7;

    const int lr = tid >> 1;
    const int lc = (tid & 1) << 1;

    const uint32_t sbase = smem_u32(sh);
    const __half* Ap = A + (size_t)(m0 + lr) * K;
    const __half* Wp = W + (size_t)(n0 + lr) * K;

    const uint32_t aoff =
        ((wm*64 + ((lane>>3)&1)*8 + (lane&7)) * GPW + (lane>>4)*4) * 4;
    const uint32_t woff =
        ((wn*32 + ((lane>>4)&1)*8 + (lane&7)) * GPW + ((lane>>3)&1)*4) * 4;

    float acc[4][4][4];
    #pragma unroll
    for (int i = 0; i < 4; i++)
        #pragma unroll
        for (int j = 0; j < 4; j++)
            #pragma unroll
            for (int c = 0; c < 4; c++) acc[i][j][c] = 0.f;

    const int nsteps = K >> 5;

    auto issue = [&](int stage, int ks) {
        const int kb = ks << 5;
        const uint32_t so = sbase + (uint32_t)(stage * 2 * STG_W * 4);
        #pragma unroll
        for (int j = 0; j < 2; j++) {
            const int c = lc + j;
            const uint32_t off = (uint32_t)((lr * GPW + c * 4) * 4);
            cp_async16(so + off, Ap + kb + c * 8);
            cp_async16(so + STG_W * 4 + off, Wp + kb + c * 8);
        }
        CP_COMMIT();
    };

    issue(0, 0);
    issue(1, 1);

    int stage = 0;
    for (int ks = 0; ks < nsteps; ks++) {
        if (ks + 1 < nsteps) CP_WAIT1(); else CP_WAIT0();
        __syncthreads();
        if (ks + 2 < nsteps) {
            int ns = stage + 2; if (ns >= 3) ns -= 3;
            issue(ns, ks + 2);
        }

        const uint32_t stb = sbase + (uint32_t)(stage * 2 * STG_W * 4);
        const uint32_t aAddr = stb + aoff;
        const uint32_t wAddr = stb + STG_W * 4 + woff;

        #pragma unroll
        for (int kt = 0; kt < 2; kt++) {
            uint32_t af[4][4], bf[4][2];
            #pragma unroll
            for (int mt = 0; mt < 4; mt++)
                LDSM4(af[mt][0], af[mt][1], af[mt][2], af[mt][3],
                      aAddr + (mt*16*GPW + kt*8) * 4);
            #pragma unroll
            for (int np = 0; np < 2; np++)
                LDSM4(bf[2*np][0], bf[2*np][1], bf[2*np+1][0], bf[2*np+1][1],
                      wAddr + (np*16*GPW + kt*8) * 4);
            #pragma unroll
            for (int mt = 0; mt < 4; mt++)
                #pragma unroll
                for (int nt = 0; nt < 4; nt++)
                    mma16(acc[mt][nt], af[mt], bf[nt][0], bf[nt][1]);
        }
        if (++stage == 3) stage = 0;
    }

    if (!ROPE) {
        #pragma unroll
        for (int nt = 0; nt < 4; nt++) {
            int col = n0 + wn*32 + nt*8 + 2*qc;
            float2 bia = *(const float2*)&bias[col];
            #pragma unroll
            for (int mt = 0; mt < 4; mt++) {
                int r0 = m0 + wm*64 + mt*16 + qr;
                float v00 = acc[mt][nt][0] + bia.x, v01 = acc[mt][nt][1] + bia.y;
                float v10 = acc[mt][nt][2] + bia.x, v11 = acc[mt][nt][3] + bia.y;
                if (sizeof(OT) == 4) {
                    *(float2*)&((float*)Cm)[(size_t)r0 * N + col]       = make_float2(v00, v01);
                    *(float2*)&((float*)Cm)[(size_t)(r0 + 8) * N + col] = make_float2(v10, v11);
                } else {
                    *(uint32_t*)&((__half*)Cm)[(size_t)r0 * N + col]       = packh2(v00, v01);
                    *(uint32_t*)&((__half*)Cm)[(size_t)(r0 + 8) * N + col] = packh2(v10, v11);
                }
            }
        }
    } else {
        // ---- stage fp16 tile in smem
        __syncthreads();
        uint32_t* St = sh; // 128 rows x 68 words
        #pragma unroll
        for (int nt = 0; nt < 4; nt++) {
            int colw = wn*16 + nt*4 + qc;
            float2 bia = *(const float2*)&bias[n0 + 2*colw];
            #pragma unroll
            for (int mt = 0; mt < 4; mt++) {
                int r0 = wm*64 + mt*16 + qr;
                St[r0*68 + colw]     = packh2(acc[mt][nt][0]+bia.x, acc[mt][nt][1]+bia.y);
                St[(r0+8)*68 + colw] = packh2(acc[mt][nt][2]+bia.x, acc[mt][nt][3]+bia.y);
            }
        }
        __syncthreads();

        // ---- streaming coalesced scatter
        const int c  = tid & 7;
        const int u0 = tid >> 3;
        const int d0 = c * 8;
        const float sgn = (c < 4) ? -1.f : 1.f;

        #pragma unroll 2
        for (int p = 0; p < 8; p++) {
            const int u  = p * 32 + u0;
            const int r  = u >> 1, hh = u & 1;
            const int hd = (n0 >> 6) + hh;
            const int g  = hd / 6, sl = hd % 6;
            const int rowg = m0 + r;
            const int t  = rowg & (Tc - 1);
            const int bb = rowg >> 11;
            const int bgq = bb * NGc + g;
            const uint32_t* src = St + r*68 + hh*32;

            uint4 own = *(const uint4*)(src + c*4);
            if (sl == QPKc + 1) {
                __half* dst = g_v + ((size_t)bgq*Tc + t)*HSc + d0;
                *(uint4*)dst = own;
            } else {
                uint4 par = *(const uint4*)(src + (c^4)*4);
                const float scl = (sl < QPKc) ? QSCALE : 1.f;
                float4 cA = *(const float4*)&cosb[t*64 + d0];
                float4 cB = *(const float4*)&cosb[t*64 + d0 + 4];
                float4 sA = *(const float4*)&sinb[t*64 + d0];
                float4 sB = *(const float4*)&sinb[t*64 + d0 + 4];
                const uint32_t* ow = (const uint32_t*)&own;
                const uint32_t* pw = (const uint32_t*)&par;
                uint4 o;
                uint32_t* oo = (uint32_t*)&o;
                const float cc[8] = {cA.x,cA.y,cA.z,cA.w,cB.x,cB.y,cB.z,cB.w};
                const float ss[8] = {sA.x,sA.y,sA.z,sA.w,sB.x,sB.y,sB.z,sB.w};
                #pragma unroll
                for (int j = 0; j < 4; j++) {
                    __half2 oh = *(const __half2*)&ow[j];
                    __half2 ph = *(const __half2*)&pw[j];
                    float f0 = __low2float(oh), f1 = __high2float(oh);
                    float p0 = __low2float(ph), p1 = __high2float(ph);
                    oo[j] = packh2((f0*cc[2*j]   + sgn*p0*ss[2*j])  *scl,
                                   (f1*cc[2*j+1] + sgn*p1*ss[2*j+1])*scl);
                }
                __half* dst = (sl < QPKc)
                    ? g_qh + (((size_t)bgq*QPKc + sl)*Tc + t)*HSc + d0
                    : g_kh + ((size_t)bgq*Tc + t)*HSc + d0;
                *(uint4*)dst = o;
            }
        }
    }
}

// ---------------------------------------------------------------------------
// Attention tile body — compile-time LIM (key-group limit) and MASKT.
// ---------------------------------------------------------------------------
#define PW 36
#define AQ_W   (128 * PW)
#define AKV_W  (64 * PW)
#define ASMEM  ((AQ_W + 4 * AKV_W) * 4)   // 55296 bytes

template <int LIM, bool MASKT>
__device__ __forceinline__ void attn_tile(
    uint32_t qAddr, uint32_t kAddr, uint32_t vAddr, uint32_t oAddr,
    int s0, int wrow_min, int qr, int qc,
    float (&co)[8][4], float (&co_l)[4], float (&mrow)[2])
{
    constexpr int NT = 2 * (LIM + 1);
    float cs[NT][4];
    #pragma unroll
    for (int nt = 0; nt < NT; nt++)
        #pragma unroll
        for (int c = 0; c < 4; c++) cs[nt][c] = 0.f;

    #pragma unroll
    for (int kt = 0; kt < 4; kt++) {
        uint32_t a[4];
        LDSM4(a[0], a[1], a[2], a[3], qAddr + kt*32);
        #pragma unroll
        for (int np = 0; np <= LIM; np++) {
            uint32_t b0, b1, b2, b3;
            LDSM4(b0, b1, b2, b3, kAddr + (np*16*PW + kt*8) * 4);
            mma16(cs[2*np],   a, b0, b1);
            mma16(cs[2*np+1], a, b2, b3);
        }
    }

    const int r0g = wrow_min + qr;
    const int r1g = r0g + 8;
    float mx0 = mrow[0], mx1 = mrow[1];
    #pragma unroll
    for (int nt = 0; nt < NT; nt++) {
        int cbk = s0 + nt*8 + 2*qc;
        if (MASKT) {
            if (cbk     > r0g) cs[nt][0] = -1e30f;
            if (cbk + 1 > r0g) cs[nt][1] = -1e30f;
            if (cbk     > r1g) cs[nt][2] = -1e30f;
            if (cbk + 1 > r1g) cs[nt][3] = -1e30f;
        }
        mx0 = fmaxf(mx0, fmaxf(cs[nt][0], cs[nt][1]));
        mx1 = fmaxf(mx1, fmaxf(cs[nt][2], cs[nt][3]));
    }
    mx0 = fmaxf(mx0, __shfl_xor_sync(0xffffffffu, mx0, 1));
    mx0 = fmaxf(mx0, __shfl_xor_sync(0xffffffffu, mx0, 2));
    mx1 = fmaxf(mx1, __shfl_xor_sync(0xffffffffu, mx1, 1));
    mx1 = fmaxf(mx1, __shfl_xor_sync(0xffffffffu, mx1, 2));

    float al0 = exp2f(mrow[0] - mx0);
    float al1 = exp2f(mrow[1] - mx1);
    mrow[0] = mx0; mrow[1] = mx1;

    uint32_t pa[LIM + 1][4];
    #pragma unroll
    for (int nt = 0; nt < NT; nt++) {
        uint32_t p01 = exp2h2(cs[nt][0] - mx0, cs[nt][1] - mx0);
        uint32_t p23 = exp2h2(cs[nt][2] - mx1, cs[nt][3] - mx1);
        pa[nt >> 1][(nt & 1) << 1]       = p01;
        pa[nt >> 1][((nt & 1) << 1) + 1] = p23;
    }

    #pragma unroll
    for (int nt = 0; nt < 8; nt++) {
        co[nt][0] *= al0; co[nt][1] *= al0;
        co[nt][2] *= al1; co[nt][3] *= al1;
    }
    co_l[0] *= al0; co_l[1] *= al0;
    co_l[2] *= al1; co_l[3] *= al1;

    #pragma unroll
    for (int kt = 0; kt <= LIM; kt++) {
        #pragma unroll
        for (int np = 0; np < 4; np++) {
            uint32_t b0, b1, b2, b3;
            LDSM4T(b0, b1, b2, b3, vAddr + (kt*16*PW + np*8) * 4);
            mma16(co[2*np],   pa[kt], b0, b1);
            mma16(co[2*np+1], pa[kt], b2, b3);
        }
        uint32_t o0, o1;
        LDSM2T(o0, o1, oAddr + kt*16*PW*4);
        mma16(co_l, pa[kt], o0, o1);
    }
}

// ---------------------------------------------------------------------------
// Flash attention + piggybacked proj_w conversion (blockIdx.y == QPKc).
// ---------------------------------------------------------------------------
__global__ __launch_bounds__(256, 2) void attn_h(
    const float* __restrict__ pw_src, __half* __restrict__ pw_dst)
{
    extern __shared__ uint32_t ash[];
    uint32_t* Qs = ash;

    const int tid  = threadIdx.x;

    // ---- piggyback blocks: convert a proj_w chunk and exit --------------
    if (blockIdx.y == QPKc) {
        const int bid = blockIdx.z * gridDim.x + blockIdx.x;   // 0..255
        const size_t base = (size_t)bid * 16384;
        #pragma unroll
        for (int it = 0; it < 8; it++) {
            const size_t i = base + (size_t)it * 2048 + tid * 8;
            float4 v0 = *(const float4*)(pw_src + i);
            float4 v1 = *(const float4*)(pw_src + i + 4);
            uint4 o;
            o.x = packh2(v0.x, v0.y); o.y = packh2(v0.z, v0.w);
            o.z = packh2(v1.x, v1.y); o.w = packh2(v1.z, v1.w);
            *(uint4*)&pw_dst[i] = o;
        }
        return;
    }

    const int lane = tid & 31;
    const int warp = tid >> 5;
    const int qr = lane >> 2;
    const int qc = lane & 3;

    const int q0   = (gridDim.x - 1 - blockIdx.x) << 7;
    const int slot = blockIdx.y;
    const int bg   = blockIdx.z;
    const int b = bg >> 3, gg = bg & 7;

    const __half* Qp = g_qh + ((size_t)(bg * QPKc + slot) * Tc + q0) * HSc;
    const __half* Kp = g_kh + (size_t)bg * Tc * HSc;
    const __half* Vp = g_v  + (size_t)bg * Tc * HSc;

    const uint32_t sb = smem_u32(ash);
    const uint32_t kwb[2] = { AQ_W,           AQ_W + 2*AKV_W };
    const uint32_t vwb[2] = { AQ_W + AKV_W,   AQ_W + 3*AKV_W };

    const uint32_t qAddr = sb +
        ((warp*16 + ((lane>>3)&1)*8 + (lane&7)) * PW + (lane>>4)*4) * 4;
    const uint32_t kOff =
        ((((lane>>4)&1)*8 + (lane&7)) * PW + ((lane>>3)&1)*4) * 4;
    const uint32_t vOff =
        ((((lane&7) + ((lane>>3)&1)*8) * PW) + ((lane>>4)&1)*4) * 4;
    const uint32_t oOff =
        ((((lane&7) + ((lane>>3)&1)*8) * PW) + 32) * 4;

    const int lrr = tid >> 2, lcq = tid & 3;

    auto issueKV = [&](int s, int st) {
        const int s0 = st << 6;
        const __half* kp = Kp + (size_t)(s0 + lrr) * HSc;
        const __half* vp = Vp + (size_t)(s0 + lrr) * HSc;
        const uint32_t kd = sb + (kwb[s] + lrr * PW) * 4;
        const uint32_t vd = sb + (vwb[s] + lrr * PW) * 4;
        #pragma unroll
        for (int j = 0; j < 2; j++) {
            const int c = lcq + 4 * j;
            cp_async16(kd + c * 16, kp + c * 8);
            cp_async16(vd + c * 16, vp + c * 8);
        }
        CP_COMMIT();
    };

    issueKV(0, 0);

    for (int i = tid; i < 128; i += 256) {
        int r = i & 63, s = i >> 6;
        uint32_t* p = ash + vwb[s] + r * PW + 32;
        p[0] = 0x3C003C00u; p[1] = 0x3C003C00u;
        p[2] = 0x3C003C00u; p[3] = 0x3C003C00u;
    }

    {
        const int r = tid >> 1, cq = tid & 1;
        #pragma unroll
        for (int j = 0; j < 4; j++) {
            int c = cq + 2 * j;
            uint4 v = *(const uint4*)(Qp + r * HSc + c * 8);
            *(uint4*)&Qs[r * PW + c * 4] = v;
        }
    }

    float co[8][4], co_l[4];
    #pragma unroll
    for (int nt = 0; nt < 8; nt++)
        #pragma unroll
        for (int c = 0; c < 4; c++) co[nt][c] = 0.f;
    #pragma unroll
    for (int c = 0; c < 4; c++) co_l[c] = 0.f;

    float mrow[2] = {-INFINITY, -INFINITY};

    const int ntiles = (q0 >> 6) + 2;
    const int wrow_min = q0 + warp*16;
    const int wrow_max = wrow_min + 15;

    for (int st = 0; st < ntiles; st++) {
        const int s0 = st << 6;
        const int cur = st & 1;

        CP_WAIT0();
        __syncthreads();
        if (st + 1 < ntiles) issueKV(cur ^ 1, st + 1);

        const int d = wrow_max - s0;      // always == 15 (mod 16)
        if (d < 0) continue;

        const uint32_t kAddr = sb + kwb[cur] * 4 + kOff;
        const uint32_t vAddr = sb + vwb[cur] * 4 + vOff;
        const uint32_t oAddr = sb + vwb[cur] * 4 + oOff;

        if (d >= 64) {
            attn_tile<3, false>(qAddr, kAddr, vAddr, oAddr,
                                s0, wrow_min, qr, qc, co, co_l, mrow);
        } else {
            switch (d >> 4) {
            case 3: attn_tile<3, true>(qAddr, kAddr, vAddr, oAddr,
                                       s0, wrow_min, qr, qc, co, co_l, mrow); break;
            case 2: attn_tile<2, true>(qAddr, kAddr, vAddr, oAddr,
                                       s0, wrow_min, qr, qc, co, co_l, mrow); break;
            case 1: attn_tile<1, true>(qAddr, kAddr, vAddr, oAddr,
                                       s0, wrow_min, qr, qc, co, co_l, mrow); break;
            default: attn_tile<0, true>(qAddr, kAddr, vAddr, oAddr,
                                        s0, wrow_min, qr, qc, co, co_l, mrow); break;
            }
        }
    }

    const float il0 = 1.f / co_l[0];
    const float il1 = 1.f / co_l[2];
    const int head = gg * QPKc + slot;
    const int r0g = q0 + warp*16 + qr;
    #pragma unroll
    for (int nt = 0; nt < 8; nt++) {
        int d = nt*8 + 2*qc;
        size_t o0 = ((size_t)(b * Tc + r0g)     * NHc + head) * HSc + d;
        size_t o1 = ((size_t)(b * Tc + r0g + 8) * NHc + head) * HSc + d;
        *(uint32_t*)&g_yh[o0] = packh2(co[nt][0] * il0, co[nt][1] * il0);
        *(uint32_t*)&g_yh[o1] = packh2(co[nt][2] * il1, co[nt][3] * il1);
    }
}

// ---------------------------------------------------------------------------
extern "C" void kernel_launch(void* const* d_in, const int* in_sizes, int n_in,
                              void* d_out, int out_size)
{
    const float* x      = (const float*)d_in[0];
    const float* cosb   = (const float*)d_in[1];
    const float* sinb   = (const float*)d_in[2];
    const float* attn_w = (const float*)d_in[3];
    const float* attn_b = (const float*)d_in[4];
    const float* proj_w = (const float*)d_in[5];
    const float* proj_b = (const float*)d_in[6];
    float* out = (float*)d_out;

    __half *xh, *awh, *pwh, *yh;
    cudaGetSymbolAddress((void**)&xh,  g_xh);
    cudaGetSymbolAddress((void**)&awh, g_awh);
    cudaGetSymbolAddress((void**)&pwh, g_pwh);
    cudaGetSymbolAddress((void**)&yh,  g_yh);

    cudaFuncSetAttribute((gemm_h<__half, true>),
                         cudaFuncAttributeMaxDynamicSharedMemorySize, GSMEM);
    cudaFuncSetAttribute((gemm_h<float, false>),
                         cudaFuncAttributeMaxDynamicSharedMemorySize, GSMEM);
    cudaFuncSetAttribute(attn_h,
                         cudaFuncAttributeMaxDynamicSharedMemorySize, ASMEM);

    // 0. fp32 -> fp16 converts: x + attn_w only (proj_w piggybacks on attn)
    {
        int na = BTc * Cc, nb = QKVD * Cc;
        int tot = na + nb;
        cvt2_kernel<<<tot/8/256, 256>>>(x, xh, na, attn_w, awh, nb);
    }

    // 1. QKV GEMM with fused, coalesced rope epilogue -> g_qh / g_kh / g_v
    gemm_h<__half, true><<<dim3(QKVD/128, BTc/128), 256, GSMEM>>>(
        xh, awh, attn_b, (__half*)nullptr, cosb, sinb, BTc, QKVD, Cc);

    // 2. Flash attention (+ proj_w conversion blocks at y == QPKc)
    attn_h<<<dim3(Tc/128, QPKc + 1, Bc*NGc), 256, ASMEM>>>(proj_w, pwh);

    // 3. Output projection (fp32 out)
    gemm_h<float, false><<<dim3(Cc/128, BTc/128), 256, GSMEM>>>(
        yh, pwh, proj_b, out, nullptr, nullptr, BTc, Cc, Cc);
}